// round 1
// baseline (speedup 1.0000x reference)
#include <cuda_runtime.h>

#define NCH 30
#define ROWS_PER_BLOCK 256
#define BLOCK_THREADS 256

// FILTERS is a fixed compile-time constant in the reference — bake it in.
__constant__ float c_FILT[6][NCH] = {
    {1,1,1,1,1,1,1,1,1,1,1,1,1,1,1,1,1,1,1,1,1,1,0,0,0,0,0,0,1,1},
    {1,1,0,0,0,0,0,0,0,0,0,0,0,0,0,0,1,1,1,1,1,1,0,0,1,1,1,1,1,1},
    {1,1,0,0,1,1,0,0,1,1,0,0,1,1,0,0,0,0,0,0,0,0,0,0,0,0,0,0,1,1},
    {1,1,0,0,0,0,0,0,0,0,0,0,0,0,1,1,1,1,1,1,1,1,0,0,0,0,1,1,1,1},
    {1,1,0,0,1,0,0,0,0,0,0,0,0,0,0,0,0,0,0,0,0,0,0,0,0,0,0,0,1,1},
    {1,1,1,1,0,0,1,1,0,0,1,1,0,0,0,0,0,0,0,0,0,0,0,0,0,0,0,0,1,1}
};

// Packed shared-weight offsets
// [0:72)   W1  (6,6,2)
// [72:108) b1  (6,6)
// [108:252) W2 (6,4,6)
// [252:276) b2 (6,4)
// [276:372) W3 (6,4,4)
// [372:396) b3 (6,4)
// [396:420) Wo (6,4)
// [420:426) bo (6)

__global__ void __launch_bounds__(BLOCK_THREADS)
ext_kernel(const float* __restrict__ tpl,
           const float* __restrict__ cons,
           const float* __restrict__ w_gas,
           const float* __restrict__ W1, const float* __restrict__ b1,
           const float* __restrict__ W2, const float* __restrict__ b2,
           const float* __restrict__ W3, const float* __restrict__ b3,
           const float* __restrict__ Wo, const float* __restrict__ bo,
           float* __restrict__ out, int N)
{
    __shared__ __align__(16) float tab[NCH * 8];       // exp(w_gas[k,c]) * (k<2 ? 1 : FILT[k-2,c]), layout [c][k]
    __shared__ float s_sh[ROWS_PER_BLOCK][6];
    __shared__ float wsh[426];

    const int t = threadIdx.x;

    // ---- stage weights ----
    if (t < 72)  wsh[t]       = W1[t];
    if (t < 36)  wsh[72 + t]  = b1[t];
    if (t < 144) wsh[108 + t] = W2[t];
    if (t < 24)  wsh[252 + t] = b2[t];
    if (t < 96)  wsh[276 + t] = W3[t];
    if (t < 24)  wsh[372 + t] = b3[t];
    if (t < 24)  wsh[396 + t] = Wo[t];
    if (t < 6)   wsh[420 + t] = bo[t];

    // ---- fused exp(w_gas)*filter table: tab[c*8+k] ----
    if (t < NCH * 8) {
        int c = t >> 3;
        int k = t & 7;
        float e = expf(w_gas[k * NCH + c]);   // w_gas is (8, NCH) row-major
        float f = (k < 2) ? 1.0f : c_FILT[k - 2][c];
        tab[t] = e * f;
    }
    __syncthreads();

    // ---- Phase A: per-row tiny MLP -> 6 sigmoid gates ----
    const long base = (long)blockIdx.x * ROWS_PER_BLOCK;
    const long n = base + t;
    if (n < N) {
        const float x0 = tpl[n * 3 + 0];
        const float x1 = tpl[n * 3 + 1];

        #pragma unroll
        for (int g = 0; g < 6; g++) {
            float h1[6];
            #pragma unroll
            for (int h = 0; h < 6; h++) {
                float v = fmaf(wsh[g * 12 + h * 2], x0,
                          fmaf(wsh[g * 12 + h * 2 + 1], x1, wsh[72 + g * 6 + h]));
                h1[h] = fmaxf(v, 0.0f);
            }
            float h2[4];
            #pragma unroll
            for (int o = 0; o < 4; o++) {
                float acc = wsh[252 + g * 4 + o];
                #pragma unroll
                for (int h = 0; h < 6; h++)
                    acc = fmaf(wsh[108 + g * 24 + o * 6 + h], h1[h], acc);
                h2[o] = fmaxf(acc, 0.0f);
            }
            float h3[4];
            #pragma unroll
            for (int p = 0; p < 4; p++) {
                float acc = wsh[372 + g * 4 + p];
                #pragma unroll
                for (int h = 0; h < 4; h++)
                    acc = fmaf(wsh[276 + g * 16 + p * 4 + h], h2[h], acc);
                h3[p] = fmaxf(acc, 0.0f);
            }
            float z = wsh[420 + g];
            #pragma unroll
            for (int p = 0; p < 4; p++)
                z = fmaf(wsh[396 + g * 4 + p], h3[p], z);
            s_sh[t][g] = 1.0f / (1.0f + __expf(-z));
        }
    }
    __syncthreads();

    // ---- Phase B: streamed elementwise output ----
    // out[n][c][k]; row = 240 floats = 60 float4. float4 f: c = f>>1, k-base = (f&1)*4.
    const float4* __restrict__ cons4 = (const float4*)cons;
    const float4* __restrict__ tab4  = (const float4*)tab;   // tab4[f] == tab[c][kbase..kbase+3]
    float4* __restrict__ out4 = (float4*)out;

    int rows = (int)min((long)ROWS_PER_BLOCK, (long)N - base);
    if (rows <= 0) return;
    const int total = rows * 60;

    for (int i = t; i < total; i += BLOCK_THREADS) {
        const int r = i / 60;
        const int f = i - r * 60;
        const int half = f & 1;
        const long nn = base + r;

        float4 cv = __ldcs(&cons4[nn * 2 + half]);
        float4 tb = tab4[f];
        float4 o;
        if (half == 0) {
            o.x = cv.x * tb.x;
            o.y = cv.y * tb.y;
            o.z = cv.z * tb.z * s_sh[r][0];
            o.w = cv.w * tb.w * s_sh[r][1];
        } else {
            o.x = cv.x * tb.x * s_sh[r][2];
            o.y = cv.y * tb.y * s_sh[r][3];
            o.z = cv.z * tb.z * s_sh[r][4];
            o.w = cv.w * tb.w * s_sh[r][5];
        }
        __stcs(&out4[nn * 60 + f], o);
    }
}

extern "C" void kernel_launch(void* const* d_in, const int* in_sizes, int n_in,
                              void* d_out, int out_size)
{
    const float* tpl   = (const float*)d_in[0];
    const float* cons  = (const float*)d_in[1];
    const float* w_gas = (const float*)d_in[2];
    const float* W1    = (const float*)d_in[3];
    const float* b1    = (const float*)d_in[4];
    const float* W2    = (const float*)d_in[5];
    const float* b2    = (const float*)d_in[6];
    const float* W3    = (const float*)d_in[7];
    const float* b3    = (const float*)d_in[8];
    const float* Wo    = (const float*)d_in[9];
    const float* bo    = (const float*)d_in[10];

    const int N = in_sizes[0] / 3;
    const int blocks = (N + ROWS_PER_BLOCK - 1) / ROWS_PER_BLOCK;

    ext_kernel<<<blocks, BLOCK_THREADS>>>(tpl, cons, w_gas, W1, b1, W2, b2, W3, b3,
                                          Wo, bo, (float*)d_out, N);
}

// round 2
// speedup vs baseline: 1.4821x; 1.4821x over previous
#include <cuda_runtime.h>

#define NCH 30
#define ROWS_PER_BLOCK 240
#define BLOCK_THREADS 240

// FILTERS is a fixed compile-time constant in the reference — bake it in.
__constant__ float c_FILT[6][NCH] = {
    {1,1,1,1,1,1,1,1,1,1,1,1,1,1,1,1,1,1,1,1,1,1,0,0,0,0,0,0,1,1},
    {1,1,0,0,0,0,0,0,0,0,0,0,0,0,0,0,1,1,1,1,1,1,0,0,1,1,1,1,1,1},
    {1,1,0,0,1,1,0,0,1,1,0,0,1,1,0,0,0,0,0,0,0,0,0,0,0,0,0,0,1,1},
    {1,1,0,0,0,0,0,0,0,0,0,0,0,0,1,1,1,1,1,1,1,1,0,0,0,0,1,1,1,1},
    {1,1,0,0,1,0,0,0,0,0,0,0,0,0,0,0,0,0,0,0,0,0,0,0,0,0,0,0,1,1},
    {1,1,1,1,0,0,1,1,0,0,1,1,0,0,0,0,0,0,0,0,0,0,0,0,0,0,0,0,1,1}
};

// Packed shared-weight offsets
// [0:72)   W1  (6,6,2)
// [72:108) b1  (6,6)
// [108:252) W2 (6,4,6)
// [252:276) b2 (6,4)
// [276:372) W3 (6,4,4)
// [372:396) b3 (6,4)
// [396:420) Wo (6,4)
// [420:426) bo (6)

__global__ void __launch_bounds__(BLOCK_THREADS)
ext_kernel(const float* __restrict__ tpl,
           const float* __restrict__ cons,
           const float* __restrict__ w_gas,
           const float* __restrict__ W1, const float* __restrict__ b1,
           const float* __restrict__ W2, const float* __restrict__ b2,
           const float* __restrict__ W3, const float* __restrict__ b3,
           const float* __restrict__ Wo, const float* __restrict__ bo,
           float* __restrict__ out, int N)
{
    __shared__ __align__(16) float tab[NCH * 8];              // exp(w_gas[k,c]) * filt, layout [c][k]
    __shared__ __align__(16) float p_sh[ROWS_PER_BLOCK][8];   // cons[k] * gate[k] per row
    __shared__ float wsh[426];

    const int t = threadIdx.x;
    const int base = blockIdx.x * ROWS_PER_BLOCK;

    // ---- stage weights ----
    if (t < 72)  wsh[t]       = W1[t];
    if (t < 36)  wsh[72 + t]  = b1[t];
    if (t < 144) wsh[108 + t] = W2[t];
    if (t < 24)  wsh[252 + t] = b2[t];
    if (t < 96)  wsh[276 + t] = W3[t];
    if (t < 24)  wsh[372 + t] = b3[t];
    if (t < 24)  wsh[396 + t] = Wo[t];
    if (t < 6)   wsh[420 + t] = bo[t];

    // ---- fused exp(w_gas)*filter table: tab[c*8+k], 240 entries = 1 per thread ----
    {
        int c = t >> 3;
        int k = t & 7;
        float e = expf(w_gas[k * NCH + c]);   // w_gas is (8, NCH) row-major
        float f = (k < 2) ? 1.0f : c_FILT[k - 2][c];
        tab[t] = e * f;
    }
    __syncthreads();

    // ---- Phase A: per-row tiny MLP -> gates, fold into p[k] = cons[k]*gate[k] ----
    const int n = base + t;
    if (n < N) {
        const float x0 = tpl[n * 3 + 0];
        const float x1 = tpl[n * 3 + 1];

        float s[6];
        #pragma unroll
        for (int g = 0; g < 6; g++) {
            float h1[6];
            #pragma unroll
            for (int h = 0; h < 6; h++) {
                float v = fmaf(wsh[g * 12 + h * 2], x0,
                          fmaf(wsh[g * 12 + h * 2 + 1], x1, wsh[72 + g * 6 + h]));
                h1[h] = fmaxf(v, 0.0f);
            }
            float h2[4];
            #pragma unroll
            for (int o = 0; o < 4; o++) {
                float acc = wsh[252 + g * 4 + o];
                #pragma unroll
                for (int h = 0; h < 6; h++)
                    acc = fmaf(wsh[108 + g * 24 + o * 6 + h], h1[h], acc);
                h2[o] = fmaxf(acc, 0.0f);
            }
            float h3[4];
            #pragma unroll
            for (int p = 0; p < 4; p++) {
                float acc = wsh[372 + g * 4 + p];
                #pragma unroll
                for (int h = 0; h < 4; h++)
                    acc = fmaf(wsh[276 + g * 16 + p * 4 + h], h2[h], acc);
                h3[p] = fmaxf(acc, 0.0f);
            }
            float z = wsh[420 + g];
            #pragma unroll
            for (int p = 0; p < 4; p++)
                z = fmaf(wsh[396 + g * 4 + p], h3[p], z);
            s[g] = 1.0f / (1.0f + __expf(-z));
        }

        const float4* cons4 = (const float4*)cons;
        float4 c0 = cons4[n * 2 + 0];
        float4 c1 = cons4[n * 2 + 1];
        float4 p0, p1;
        p0.x = c0.x;          // k=0 gate=1
        p0.y = c0.y;          // k=1 gate=1
        p0.z = c0.z * s[0];   // k=2
        p0.w = c0.w * s[1];   // k=3
        p1.x = c1.x * s[2];   // k=4
        p1.y = c1.y * s[3];   // k=5
        p1.z = c1.z * s[4];   // k=6
        p1.w = c1.w * s[5];   // k=7
        ((float4*)p_sh[t])[0] = p0;
        ((float4*)p_sh[t])[1] = p1;
    }
    __syncthreads();

    // ---- Phase B: streamed output. f = t%60 fixed per thread -> tab in register. ----
    const int f  = t % 60;      // float4 index within the 240-float row
    const int r0 = t / 60;      // starting row within the block (0..3)
    const float4 tb = ((const float4*)tab)[f];

    const float4* pp = (const float4*)p_sh + (r0 * 2 + (f & 1));
    float4* op = (float4*)out + ((base + r0) * 60 + f);

    const int rows = min(ROWS_PER_BLOCK, N - base);
    if (rows == ROWS_PER_BLOCK) {
        #pragma unroll
        for (int it = 0; it < ROWS_PER_BLOCK / 4; it++) {
            float4 p = pp[it * 8];                 // 4 rows * 2 float4 stride
            float4 o;
            o.x = p.x * tb.x;
            o.y = p.y * tb.y;
            o.z = p.z * tb.z;
            o.w = p.w * tb.w;
            __stcs(op + it * 240, o);              // 4 rows * 60 float4 stride
        }
    } else {
        for (int r = r0; r < rows; r += 4) {
            float4 p = *pp;
            float4 o;
            o.x = p.x * tb.x;
            o.y = p.y * tb.y;
            o.z = p.z * tb.z;
            o.w = p.w * tb.w;
            __stcs(op, o);
            pp += 8;
            op += 240;
        }
    }
}

extern "C" void kernel_launch(void* const* d_in, const int* in_sizes, int n_in,
                              void* d_out, int out_size)
{
    const float* tpl   = (const float*)d_in[0];
    const float* cons  = (const float*)d_in[1];
    const float* w_gas = (const float*)d_in[2];
    const float* W1    = (const float*)d_in[3];
    const float* b1    = (const float*)d_in[4];
    const float* W2    = (const float*)d_in[5];
    const float* b2    = (const float*)d_in[6];
    const float* W3    = (const float*)d_in[7];
    const float* b3    = (const float*)d_in[8];
    const float* Wo    = (const float*)d_in[9];
    const float* bo    = (const float*)d_in[10];

    const int N = in_sizes[0] / 3;
    const int blocks = (N + ROWS_PER_BLOCK - 1) / ROWS_PER_BLOCK;

    ext_kernel<<<blocks, BLOCK_THREADS>>>(tpl, cons, w_gas, W1, b1, W2, b2, W3, b3,
                                          Wo, bo, (float*)d_out, N);
}